// round 6
// baseline (speedup 1.0000x reference)
#include <cuda_runtime.h>
#include <cuda_bf16.h>

// B=32 images of 512x512 fp32 (output, density_map), 3 int64 bboxes/batch.
// Single kernel: streaming pass + last-block finalization.
// R6: revert streaming structure to R1's fast shape (grid 4096, 2 float4
// iters/thread, occ 8 / 32 regs) while keeping the fused last-block finalize.

#define IMG_H 512
#define IMG_W 512
#define HW (IMG_H * IMG_W)        // 262144
#define NBATCH 32
#define NBOX 3
#define BPB 128                   // blocks per batch
#define NB (NBATCH * BPB)         // 4096 blocks
// each block: 512 float4 = 2048 elems

__device__ float g_sq[NB];
__device__ float g_bd[NB];
__device__ float g_box[NBOX][NB];
__device__ unsigned int g_count;  // zero-init at load; reset by last block

__global__ __launch_bounds__(256, 8)
void crit_kernel(const float* __restrict__ out_p,
                 const float* __restrict__ dmp_p,
                 const long long* __restrict__ bbox_p,
                 float* __restrict__ out3,
                 const unsigned char* __restrict__ nobj_ptr)
{
    const int bid = blockIdx.x;
    const int b   = bid >> 7;     // batch
    const int blk = bid & 127;    // block within batch
    const int t   = threadIdx.x;
    const int wid = t >> 5, lid = t & 31;

    // Load + clip this batch's 3 bboxes into shared
    __shared__ int sbb[NBOX * 4];
    if (t < NBOX * 4) {
        long long v = bbox_p[(size_t)b * NBOX * 4 + t];
        if (v < 0) v = 0;
        if (v > IMG_W) v = IMG_W;
        sbb[t] = (int)v;
    }
    __syncthreads();

    int bx1[NBOX], by1[NBOX], bx2[NBOX], by2[NBOX];
#pragma unroll
    for (int j = 0; j < NBOX; j++) {
        bx1[j] = sbb[j * 4 + 0];
        by1[j] = sbb[j * 4 + 1];
        bx2[j] = max(sbb[j * 4 + 2], bx1[j]);
        by2[j] = max(sbb[j * 4 + 3], by1[j]);
    }

    const float4* __restrict__ o4 = (const float4*)(out_p + (size_t)b * HW);
    const float4* __restrict__ d4 = (const float4*)(dmp_p + (size_t)b * HW);

    float sq = 0.f, bd = 0.f;
    float bs[NBOX] = {0.f, 0.f, 0.f};

#pragma unroll
    for (int it = 0; it < 2; it++) {
        int i = blk * 512 + it * 256 + t;      // float4 index in [0, 65536)
        float4 o = o4[i];
        float4 d = d4[i];
        float dx = o.x - d.x, dy = o.y - d.y, dz = o.z - d.z, dw = o.w - d.w;
        sq += dx * dx + dy * dy + dz * dz + dw * dw;
        bd += (dx + dy) + (dz + dw);

        int pix = i << 2;
        int y   = pix >> 9;
        int x0  = pix & 511;
#pragma unroll
        for (int j = 0; j < NBOX; j++) {
            if (y >= by1[j] && y < by2[j]) {
                float s = 0.f;
                if (x0     >= bx1[j] && x0     < bx2[j]) s += o.x;
                if (x0 + 1 >= bx1[j] && x0 + 1 < bx2[j]) s += o.y;
                if (x0 + 2 >= bx1[j] && x0 + 2 < bx2[j]) s += o.z;
                if (x0 + 3 >= bx1[j] && x0 + 3 < bx2[j]) s += o.w;
                bs[j] += s;
            }
        }
    }

    // Block reduce 5 floats: warp shuffle, then across 8 warps via shared.
    float v5[5] = {sq, bd, bs[0], bs[1], bs[2]};
#pragma unroll
    for (int k = 0; k < 5; k++) {
#pragma unroll
        for (int off = 16; off > 0; off >>= 1)
            v5[k] += __shfl_xor_sync(0xFFFFFFFFu, v5[k], off);
    }
    __shared__ float wsum[8][5];
    if (lid == 0) {
#pragma unroll
        for (int k = 0; k < 5; k++) wsum[wid][k] = v5[k];
    }
    __syncthreads();

    __shared__ bool isLast;
    if (t == 0) {
        float a0 = 0, a1 = 0, a2 = 0, a3 = 0, a4 = 0;
#pragma unroll
        for (int w = 0; w < 8; w++) {
            a0 += wsum[w][0]; a1 += wsum[w][1]; a2 += wsum[w][2];
            a3 += wsum[w][3]; a4 += wsum[w][4];
        }
        g_sq[bid]     = a0;
        g_bd[bid]     = a1;
        g_box[0][bid] = a2;
        g_box[1][bid] = a3;
        g_box[2][bid] = a4;
        __threadfence();
        unsigned int old = atomicAdd(&g_count, 1u);
        isLast = (old == NB - 1);
    }
    __syncthreads();
    if (!isLast) return;

    // ---------- last-block finalization (partials hot in L2) ----------
    __shared__ double shd[256];
    __shared__ double sh_bd2[NBATCH];
    __shared__ double sh_m[NBATCH * NBOX];

    // dmap squared-error total: 4096 floats, 16 coalesced loads/thread
    {
        double s = 0.0;
#pragma unroll
        for (int i = 0; i < NB / 256; i++)
            s += (double)__ldcg(&g_sq[i * 256 + t]);
        shd[t] = s;
    }
    __syncthreads();
#pragma unroll
    for (int o = 128; o > 0; o >>= 1) {
        if (t < o) shd[t] += shd[t + o];
        __syncthreads();
    }
    double total_sq = shd[0];

    // count diff per batch: one warp per batch (8 warps x 4 batches),
    // each lane sums 4 partials (fixed order), then shuffle reduce.
#pragma unroll
    for (int bb = wid; bb < NBATCH; bb += 8) {
        double v = 0.0;
#pragma unroll
        for (int k = 0; k < BPB / 32; k++)
            v += (double)__ldcg(&g_bd[bb * BPB + k * 32 + lid]);
#pragma unroll
        for (int off = 16; off > 0; off >>= 1)
            v += __shfl_xor_sync(0xFFFFFFFFu, v, off);
        if (lid == 0) sh_bd2[bb] = v * v;
    }

    // box sums: one warp per (batch, box) pair (8 warps x 12 pairs)
#pragma unroll
    for (int p = wid; p < NBATCH * NBOX; p += 8) {
        int bb = p / NBOX, j = p % NBOX;
        double v = 0.0;
#pragma unroll
        for (int k = 0; k < BPB / 32; k++)
            v += (double)__ldcg(&g_box[j][bb * BPB + k * 32 + lid]);
#pragma unroll
        for (int off = 16; off > 0; off >>= 1)
            v += __shfl_xor_sync(0xFFFFFFFFu, v, off);
        if (lid == 0) {
            double r = 1.0 - v;
            sh_m[p] = (r > 0.0) ? r : 0.0;
        }
    }
    __syncthreads();

    if (wid == 0) {
        double c = sh_bd2[lid];
        double m = sh_m[lid] + sh_m[lid + 32] + sh_m[lid + 64];
#pragma unroll
        for (int off = 16; off > 0; off >>= 1) {
            c += __shfl_xor_sync(0xFFFFFFFFu, c, off);
            m += __shfl_xor_sync(0xFFFFFFFFu, m, off);
        }
        if (lid == 0) {
            // Decode num_objects robustly (int32/int64 LE, or fp32).
            double num = 96.0;
            if (nobj_ptr) {
                int iv;
                memcpy(&iv, nobj_ptr, sizeof(int));
                if (iv > 0 && iv < (1 << 26)) {
                    num = (double)iv;
                } else {
                    float fv = __int_as_float(iv);
                    if (fv > 0.5f && fv < 1e8f) num = (double)fv;
                }
            }
            out3[0] = (float)(total_sq / num);
            out3[1] = (float)(c / (double)NBATCH);
            out3[2] = (float)m;
            g_count = 0;   // reset for next graph replay
        }
    }
}

extern "C" void kernel_launch(void* const* d_in, const int* in_sizes, int n_in,
                              void* d_out, int out_size)
{
    const float*     out_p  = (const float*)d_in[0];
    const float*     dmp_p  = (const float*)d_in[1];
    const long long* bbox_p = (const long long*)d_in[2];
    const unsigned char* nobj = (n_in > 3) ? (const unsigned char*)d_in[3] : nullptr;
    (void)in_sizes; (void)out_size;

    crit_kernel<<<NB, 256>>>(out_p, dmp_p, bbox_p, (float*)d_out, nobj);
}

// round 8
// speedup vs baseline: 1.4817x; 1.4817x over previous
#include <cuda_runtime.h>
#include <cuda_bf16.h>
#include <cstdint>

// B=32 images of 512x512 fp32 (output, density_map), 3 int64 bboxes/batch.
// R7: stream via cp.async.bulk (DMA) into shared + mbarrier pipeline, compute
// from LDS. LDG path empirically capped ~2.3TB/s across all shapes; bulk-copy
// path targets the ~6300 B/cyc LTS cap. Last-block fused finalize kept.

#define IMG_H 512
#define IMG_W 512
#define HW (IMG_H * IMG_W)        // 262144
#define NBATCH 32
#define NBOX 3
#define BPB 32                    // blocks per batch
#define NB (NBATCH * BPB)         // 1024 blocks
#define SPAN 8192                 // floats per array per block
#define STAGE 1024                // floats per array per stage
#define NSTAGE (SPAN / STAGE)     // 8
#define STAGE_BYTES (STAGE * 4)   // 4096

__device__ float g_sq[NB];
__device__ float g_bd[NB];
__device__ float g_box[NBOX][NB];
__device__ unsigned int g_count;  // zero-init at load; reset by last block

__device__ __forceinline__ uint32_t smem_u32(const void* p) {
    return (uint32_t)__cvta_generic_to_shared(p);
}
__device__ __forceinline__ void mbar_init(uint32_t a, uint32_t n) {
    asm volatile("mbarrier.init.shared.b64 [%0], %1;" :: "r"(a), "r"(n) : "memory");
}
__device__ __forceinline__ void mbar_expect_tx(uint32_t a, uint32_t bytes) {
    asm volatile("mbarrier.arrive.expect_tx.shared.b64 _, [%0], %1;"
                 :: "r"(a), "r"(bytes) : "memory");
}
__device__ __forceinline__ void bulk_g2s(uint32_t dst, const void* src,
                                         uint32_t bytes, uint32_t mbar) {
    asm volatile(
        "cp.async.bulk.shared::cta.global.mbarrier::complete_tx::bytes "
        "[%0], [%1], %2, [%3];"
        :: "r"(dst), "l"(src), "r"(bytes), "r"(mbar) : "memory");
}
__device__ __forceinline__ void mbar_wait(uint32_t a, uint32_t phase) {
    uint32_t done;
    do {
        asm volatile(
            "{\n\t.reg .pred p;\n\t"
            "mbarrier.try_wait.parity.shared.b64 p, [%1], %2, 0x989680;\n\t"
            "selp.b32 %0, 1, 0, p;\n\t}"
            : "=r"(done) : "r"(a), "r"(phase) : "memory");
    } while (!done);
}

__global__ __launch_bounds__(256, 8)
void crit_kernel(const float* __restrict__ out_p,
                 const float* __restrict__ dmp_p,
                 const long long* __restrict__ bbox_p,
                 float* __restrict__ out3,
                 const unsigned char* __restrict__ nobj_ptr)
{
    const int bid = blockIdx.x;
    const int b   = bid >> 5;     // batch
    const int blk = bid & 31;     // block within batch
    const int t   = threadIdx.x;
    const int wid = t >> 5, lid = t & 31;

    __shared__ __align__(128) float so[2][STAGE];
    __shared__ __align__(128) float sd[2][STAGE];
    __shared__ __align__(8)  unsigned long long barmem[2];
    __shared__ int sbb[NBOX * 4];

    const uint32_t barA[2] = { smem_u32(&barmem[0]), smem_u32(&barmem[1]) };
    const uint32_t soA[2]  = { smem_u32(&so[0][0]),  smem_u32(&so[1][0]) };
    const uint32_t sdA[2]  = { smem_u32(&sd[0][0]),  smem_u32(&sd[1][0]) };

    // Load + clip this batch's 3 bboxes into shared
    if (t < NBOX * 4) {
        long long v = bbox_p[(size_t)b * NBOX * 4 + t];
        if (v < 0) v = 0;
        if (v > IMG_W) v = IMG_W;
        sbb[t] = (int)v;
    }
    if (t == 0) { mbar_init(barA[0], 1); mbar_init(barA[1], 1); }
    __syncthreads();

    int bx1[NBOX], by1[NBOX], bx2[NBOX], by2[NBOX];
#pragma unroll
    for (int j = 0; j < NBOX; j++) {
        bx1[j] = sbb[j * 4 + 0];
        by1[j] = sbb[j * 4 + 1];
        bx2[j] = max(sbb[j * 4 + 2], bx1[j]);
        by2[j] = max(sbb[j * 4 + 3], by1[j]);
    }

    const float* gso = out_p + (size_t)b * HW + (size_t)blk * SPAN;
    const float* gsd = dmp_p + (size_t)b * HW + (size_t)blk * SPAN;

    // Prologue: fill both pipeline stages
    if (t == 0) {
        mbar_expect_tx(barA[0], 2 * STAGE_BYTES);
        bulk_g2s(soA[0], gso,          STAGE_BYTES, barA[0]);
        bulk_g2s(sdA[0], gsd,          STAGE_BYTES, barA[0]);
        mbar_expect_tx(barA[1], 2 * STAGE_BYTES);
        bulk_g2s(soA[1], gso + STAGE,  STAGE_BYTES, barA[1]);
        bulk_g2s(sdA[1], gsd + STAGE,  STAGE_BYTES, barA[1]);
    }

    float sq = 0.f, bd = 0.f;
    float bs[NBOX] = {0.f, 0.f, 0.f};

#pragma unroll
    for (int s = 0; s < NSTAGE; s++) {
        const int buf = s & 1;
        const int ph  = (s >> 1) & 1;
        mbar_wait(barA[buf], ph);

        float4 o = ((const float4*)so[buf])[t];
        float4 d = ((const float4*)sd[buf])[t];
        float dx = o.x - d.x, dy = o.y - d.y, dz = o.z - d.z, dw = o.w - d.w;
        sq += dx * dx + dy * dy + dz * dz + dw * dw;
        bd += (dx + dy) + (dz + dw);

        int pix = blk * SPAN + s * STAGE + t * 4;   // element index in image
        int y   = pix >> 9;
        int x0  = pix & 511;
#pragma unroll
        for (int j = 0; j < NBOX; j++) {
            if (y >= by1[j] && y < by2[j]) {
                float ssum = 0.f;
                if (x0     >= bx1[j] && x0     < bx2[j]) ssum += o.x;
                if (x0 + 1 >= bx1[j] && x0 + 1 < bx2[j]) ssum += o.y;
                if (x0 + 2 >= bx1[j] && x0 + 2 < bx2[j]) ssum += o.z;
                if (x0 + 3 >= bx1[j] && x0 + 3 < bx2[j]) ssum += o.w;
                bs[j] += ssum;
            }
        }

        __syncthreads();   // all reads of buf done before refill
        if (t == 0 && s + 2 < NSTAGE) {
            mbar_expect_tx(barA[buf], 2 * STAGE_BYTES);
            bulk_g2s(soA[buf], gso + (s + 2) * STAGE, STAGE_BYTES, barA[buf]);
            bulk_g2s(sdA[buf], gsd + (s + 2) * STAGE, STAGE_BYTES, barA[buf]);
        }
    }

    // Block reduce 5 floats: warp shuffle, then across 8 warps via shared.
    float v5[5] = {sq, bd, bs[0], bs[1], bs[2]};
#pragma unroll
    for (int k = 0; k < 5; k++) {
#pragma unroll
        for (int off = 16; off > 0; off >>= 1)
            v5[k] += __shfl_xor_sync(0xFFFFFFFFu, v5[k], off);
    }
    __shared__ float wsum[8][5];
    if (lid == 0) {
#pragma unroll
        for (int k = 0; k < 5; k++) wsum[wid][k] = v5[k];
    }
    __syncthreads();

    __shared__ bool isLast;
    if (t == 0) {
        float a0 = 0, a1 = 0, a2 = 0, a3 = 0, a4 = 0;
#pragma unroll
        for (int w = 0; w < 8; w++) {
            a0 += wsum[w][0]; a1 += wsum[w][1]; a2 += wsum[w][2];
            a3 += wsum[w][3]; a4 += wsum[w][4];
        }
        g_sq[bid]     = a0;
        g_bd[bid]     = a1;
        g_box[0][bid] = a2;
        g_box[1][bid] = a3;
        g_box[2][bid] = a4;
        __threadfence();
        unsigned int old = atomicAdd(&g_count, 1u);
        isLast = (old == NB - 1);
    }
    __syncthreads();
    if (!isLast) return;

    // ---------- last-block finalization (partials hot in L2) ----------
    __shared__ double shd[256];
    __shared__ double sh_bd2[NBATCH];
    __shared__ double sh_m[NBATCH * NBOX];

    {
        double s = 0.0;
#pragma unroll
        for (int i = 0; i < NB / 256; i++)
            s += (double)__ldcg(&g_sq[i * 256 + t]);
        shd[t] = s;
    }
    __syncthreads();
#pragma unroll
    for (int o = 128; o > 0; o >>= 1) {
        if (t < o) shd[t] += shd[t + o];
        __syncthreads();
    }
    double total_sq = shd[0];

    // count diff per batch: one warp per batch (8 warps x 4 batches)
#pragma unroll
    for (int bb = wid; bb < NBATCH; bb += 8) {
        double v = (double)__ldcg(&g_bd[bb * BPB + lid]);
#pragma unroll
        for (int off = 16; off > 0; off >>= 1)
            v += __shfl_xor_sync(0xFFFFFFFFu, v, off);
        if (lid == 0) sh_bd2[bb] = v * v;
    }

    // box sums: one warp per (batch, box) pair (8 warps x 12 pairs)
#pragma unroll
    for (int p = wid; p < NBATCH * NBOX; p += 8) {
        int bb = p / NBOX, j = p % NBOX;
        double v = (double)__ldcg(&g_box[j][bb * BPB + lid]);
#pragma unroll
        for (int off = 16; off > 0; off >>= 1)
            v += __shfl_xor_sync(0xFFFFFFFFu, v, off);
        if (lid == 0) {
            double r = 1.0 - v;
            sh_m[p] = (r > 0.0) ? r : 0.0;
        }
    }
    __syncthreads();

    if (wid == 0) {
        double c = sh_bd2[lid];
        double m = sh_m[lid] + sh_m[lid + 32] + sh_m[lid + 64];
#pragma unroll
        for (int off = 16; off > 0; off >>= 1) {
            c += __shfl_xor_sync(0xFFFFFFFFu, c, off);
            m += __shfl_xor_sync(0xFFFFFFFFu, m, off);
        }
        if (lid == 0) {
            // Decode num_objects robustly (int32/int64 LE, or fp32).
            double num = 96.0;
            if (nobj_ptr) {
                int iv;
                memcpy(&iv, nobj_ptr, sizeof(int));
                if (iv > 0 && iv < (1 << 26)) {
                    num = (double)iv;
                } else {
                    float fv = __int_as_float(iv);
                    if (fv > 0.5f && fv < 1e8f) num = (double)fv;
                }
            }
            out3[0] = (float)(total_sq / num);
            out3[1] = (float)(c / (double)NBATCH);
            out3[2] = (float)m;
            g_count = 0;   // reset for next graph replay
        }
    }
}

extern "C" void kernel_launch(void* const* d_in, const int* in_sizes, int n_in,
                              void* d_out, int out_size)
{
    const float*     out_p  = (const float*)d_in[0];
    const float*     dmp_p  = (const float*)d_in[1];
    const long long* bbox_p = (const long long*)d_in[2];
    const unsigned char* nobj = (n_in > 3) ? (const unsigned char*)d_in[3] : nullptr;
    (void)in_sizes; (void)out_size;

    crit_kernel<<<NB, 256>>>(out_p, dmp_p, bbox_p, (float*)d_out, nobj);
}

// round 9
// speedup vs baseline: 2.4831x; 1.6758x over previous
#include <cuda_runtime.h>
#include <cuda_bf16.h>

// B=32 images of 512x512 fp32 (output, density_map), 3 int64 bboxes/batch.
// R9: FEW LONG STREAMS. 256 blocks, each streams a contiguous 128KB region
// per array (one batch-eighth). Theory: prior configs' 1024-4096 concurrent
// short streams caused HBM row-buffer thrash (stuck at 2.3TB/s on both LDG
// and TMA paths); the corpus 6300B/cyc measurement used ~148 streams.
// Deep LDG batching (8 in flight), last-block fused finalize kept.

#define IMG_H 512
#define IMG_W 512
#define HW (IMG_H * IMG_W)        // 262144 floats per image
#define NBATCH 32
#define NBOX 3
#define BPB 8                     // blocks per batch
#define NB (NBATCH * BPB)         // 256 blocks
#define ITERS 32                  // float4 iterations per thread per array
#define GRP 8                     // load-batch depth (8 o + 8 d = 16 LDG.128)
#define NGRP (ITERS / GRP)        // 4

__device__ float g_sq[NB];
__device__ float g_bd[NB];
__device__ float g_box[NBOX][NB];
__device__ unsigned int g_count;  // zero-init at load; reset by last block

__global__ __launch_bounds__(256, 2)
void crit_kernel(const float* __restrict__ out_p,
                 const float* __restrict__ dmp_p,
                 const long long* __restrict__ bbox_p,
                 float* __restrict__ out3,
                 const unsigned char* __restrict__ nobj_ptr)
{
    const int bid = blockIdx.x;
    const int b   = bid >> 3;     // batch
    const int e   = bid & 7;      // eighth within batch
    const int t   = threadIdx.x;
    const int wid = t >> 5, lid = t & 31;

    // Load + clip this batch's 3 bboxes into shared
    __shared__ int sbb[NBOX * 4];
    if (t < NBOX * 4) {
        long long v = bbox_p[(size_t)b * NBOX * 4 + t];
        if (v < 0) v = 0;
        if (v > IMG_W) v = IMG_W;
        sbb[t] = (int)v;
    }
    __syncthreads();

    int bx1[NBOX], by1[NBOX], bx2[NBOX], by2[NBOX];
#pragma unroll
    for (int j = 0; j < NBOX; j++) {
        bx1[j] = sbb[j * 4 + 0];
        by1[j] = sbb[j * 4 + 1];
        bx2[j] = max(sbb[j * 4 + 2], bx1[j]);
        by2[j] = max(sbb[j * 4 + 3], by1[j]);
    }

    // This block's contiguous region: float4 indices [e*8192, (e+1)*8192)
    const float4* __restrict__ o4 = (const float4*)(out_p + (size_t)b * HW);
    const float4* __restrict__ d4 = (const float4*)(dmp_p + (size_t)b * HW);
    const int base = e * (ITERS * 256) + t;

    float sq = 0.f, bd = 0.f;
    float bs[NBOX] = {0.f, 0.f, 0.f};

#pragma unroll
    for (int g = 0; g < NGRP; g++) {
        float4 o_[GRP], d_[GRP];
        // Front-batch 16 LDG.128 spanning a dense 32KB window per array.
#pragma unroll
        for (int u = 0; u < GRP; u++) {
            int i = base + (g * GRP + u) * 256;
            o_[u] = o4[i];
            d_[u] = d4[i];
        }
#pragma unroll
        for (int u = 0; u < GRP; u++) {
            float4 o = o_[u], d = d_[u];
            float dx = o.x - d.x, dy = o.y - d.y, dz = o.z - d.z, dw = o.w - d.w;
            sq += dx * dx + dy * dy + dz * dz + dw * dw;
            bd += (dx + dy) + (dz + dw);

            int i   = base + (g * GRP + u) * 256;
            int pix = i << 2;                 // element index within image
            int y   = pix >> 9;
            int x0  = pix & 511;
#pragma unroll
            for (int j = 0; j < NBOX; j++) {
                if (y >= by1[j] && y < by2[j]) {
                    float s = 0.f;
                    if (x0     >= bx1[j] && x0     < bx2[j]) s += o.x;
                    if (x0 + 1 >= bx1[j] && x0 + 1 < bx2[j]) s += o.y;
                    if (x0 + 2 >= bx1[j] && x0 + 2 < bx2[j]) s += o.z;
                    if (x0 + 3 >= bx1[j] && x0 + 3 < bx2[j]) s += o.w;
                    bs[j] += s;
                }
            }
        }
    }

    // Block reduce 5 floats: warp shuffle, then across 8 warps via shared.
    float v5[5] = {sq, bd, bs[0], bs[1], bs[2]};
#pragma unroll
    for (int k = 0; k < 5; k++) {
#pragma unroll
        for (int off = 16; off > 0; off >>= 1)
            v5[k] += __shfl_xor_sync(0xFFFFFFFFu, v5[k], off);
    }
    __shared__ float wsum[8][5];
    if (lid == 0) {
#pragma unroll
        for (int k = 0; k < 5; k++) wsum[wid][k] = v5[k];
    }
    __syncthreads();

    __shared__ bool isLast;
    if (t == 0) {
        float a0 = 0, a1 = 0, a2 = 0, a3 = 0, a4 = 0;
#pragma unroll
        for (int w = 0; w < 8; w++) {
            a0 += wsum[w][0]; a1 += wsum[w][1]; a2 += wsum[w][2];
            a3 += wsum[w][3]; a4 += wsum[w][4];
        }
        g_sq[bid]     = a0;
        g_bd[bid]     = a1;
        g_box[0][bid] = a2;
        g_box[1][bid] = a3;
        g_box[2][bid] = a4;
        __threadfence();
        unsigned int old = atomicAdd(&g_count, 1u);
        isLast = (old == NB - 1);
    }
    __syncthreads();
    if (!isLast) return;

    // ---------- last-block finalization (256 partials, L2-hot) ----------
    __shared__ double shd[256];
    __shared__ double sh_out[4];   // [0]=count_sum, [1..3]=box margins

    // dmap squared-error total: 256 floats, 1 per thread
    shd[t] = (double)__ldcg(&g_sq[t]);
    __syncthreads();
#pragma unroll
    for (int o = 128; o > 0; o >>= 1) {
        if (t < o) shd[t] += shd[t + o];
        __syncthreads();
    }
    double total_sq = shd[0];

    // warp 0: count loss. lane = batch, sum its 8 bd partials (fixed order).
    if (wid == 0) {
        double v = 0.0;
#pragma unroll
        for (int k = 0; k < BPB; k++)
            v += (double)__ldcg(&g_bd[lid * BPB + k]);
        double c = v * v;
#pragma unroll
        for (int off = 16; off > 0; off >>= 1)
            c += __shfl_xor_sync(0xFFFFFFFFu, c, off);
        if (lid == 0) sh_out[0] = c;
    }
    // warps 1-3: box j margin sums. lane = batch.
    if (wid >= 1 && wid <= 3) {
        int j = wid - 1;
        double v = 0.0;
#pragma unroll
        for (int k = 0; k < BPB; k++)
            v += (double)__ldcg(&g_box[j][lid * BPB + k]);
        double r = 1.0 - v;
        double m = (r > 0.0) ? r : 0.0;
#pragma unroll
        for (int off = 16; off > 0; off >>= 1)
            m += __shfl_xor_sync(0xFFFFFFFFu, m, off);
        if (lid == 0) sh_out[wid] = m;
    }
    __syncthreads();

    if (t == 0) {
        // Decode num_objects robustly (int32/int64 LE, or fp32).
        double num = 96.0;
        if (nobj_ptr) {
            int iv;
            memcpy(&iv, nobj_ptr, sizeof(int));
            if (iv > 0 && iv < (1 << 26)) {
                num = (double)iv;
            } else {
                float fv = __int_as_float(iv);
                if (fv > 0.5f && fv < 1e8f) num = (double)fv;
            }
        }
        out3[0] = (float)(total_sq / num);
        out3[1] = (float)(sh_out[0] / (double)NBATCH);
        out3[2] = (float)(sh_out[1] + sh_out[2] + sh_out[3]);
        g_count = 0;   // reset for next graph replay
    }
}

extern "C" void kernel_launch(void* const* d_in, const int* in_sizes, int n_in,
                              void* d_out, int out_size)
{
    const float*     out_p  = (const float*)d_in[0];
    const float*     dmp_p  = (const float*)d_in[1];
    const long long* bbox_p = (const long long*)d_in[2];
    const unsigned char* nobj = (n_in > 3) ? (const unsigned char*)d_in[3] : nullptr;
    (void)in_sizes; (void)out_size;

    crit_kernel<<<NB, 256>>>(out_p, dmp_p, bbox_p, (float*)d_out, nobj);
}